// round 7
// baseline (speedup 1.0000x reference)
#include <cuda_runtime.h>

#define N 256
#define NPH (N/2 + 2)          // 130 phase layers
#define NSTAGES (N/2)          // 128 stages; stages 1..127 followed by crossing

// Precomputed exp(i*theta) for all layers: [130][256] complex interleaved.
__device__ float2 g_phases[NPH * N];

__global__ void phase_kernel(const float* __restrict__ thetas, int n) {
    int i = blockIdx.x * blockDim.x + threadIdx.x;
    if (i < n) {
        float s, c;
        sincosf(thetas[i], &s, &c);
        g_phases[i] = make_float2(c, s);
    }
}

// One WARP per column. Lane l owns rows 8l..8l+7 as 4 complex pairs
// (X[j],Y[j]) = rows (8l+2j, 8l+2j+1) in registers. MMI/phase/MMI are
// pair-local; the crossing has 3 lane-internal couplings plus ONE complex
// exchange with each neighboring lane via warp shuffle — no smem, no barriers.
// Output: REAL PART only, row-major float32 [N][N] (verified in R5).
__global__ __launch_bounds__(32) void mesh_kernel(float* __restrict__ out) {
    const int lane = threadIdx.x;
    const int col  = blockIdx.x;

    // MMI constants: A = sqrt(1-IL)*[[T, iR],[iR, T]]
    const float AT = sqrtf(0.98f * 0.505f);
    const float AR = sqrtf(0.98f * 0.495f);
    // Crossing constants
    const float CS   = sqrtf(0.98f * 0.01f);
    const float CN   = sqrtf(0.98f * 0.99f);
    const float THRU = CN;                    // pass-through rows 0, N-1

    // Initial state: column col of diag(exp(i*theta[0]))
    float2 X[4], Y[4];
    #pragma unroll
    for (int j = 0; j < 4; j++) { X[j] = make_float2(0.f, 0.f); Y[j] = make_float2(0.f, 0.f); }
    if ((col >> 3) == lane) {
        float2 p = g_phases[col];
        int j = (col >> 1) & 3;
        if (col & 1) Y[j] = p; else X[j] = p;
    }

    // Phase table viewed as float4: one float4 = phases of rows (2m, 2m+1).
    // Layer s, lane's pair j -> index s*128 + 4*lane + j.
    const float4* __restrict__ phb = reinterpret_cast<const float4*>(g_phases);

    // Prefetch layer 1
    float4 ph[4];
    #pragma unroll
    for (int j = 0; j < 4; j++) ph[j] = phb[128 + 4 * lane + j];

    #pragma unroll 1
    for (int s = 1; s <= NSTAGES; s++) {
        // Prefetch next layer (s+1 <= 129 always valid; layer 129 = final diag)
        float4 phn[4];
        #pragma unroll
        for (int j = 0; j < 4; j++) phn[j] = phb[(s + 1) * 128 + 4 * lane + j];

        // --- MMI . phase . MMI on each pair (pair-local, 4-way ILP) ---
        #pragma unroll
        for (int j = 0; j < 4; j++) {
            float2 x = X[j], y = Y[j];
            float4 p = ph[j];               // p0 = (p.x,p.y), p1 = (p.z,p.w)

            float x1r = AT * x.x - AR * y.y;
            float x1i = AT * x.y + AR * y.x;
            float y1r = AT * y.x - AR * x.y;
            float y1i = AT * y.y + AR * x.x;

            float x2r = p.x * x1r - p.y * x1i;
            float x2i = p.x * x1i + p.y * x1r;
            float y2r = p.z * y1r - p.w * y1i;
            float y2i = p.z * y1i + p.w * y1r;

            X[j].x = AT * x2r - AR * y2i;
            X[j].y = AT * x2i + AR * y2r;
            Y[j].x = AT * y2r - AR * x2i;
            Y[j].y = AT * y2i + AR * x2r;
        }

        if (s < NSTAGES) {
            // --- crossing: pairs (2k+1, 2k+2); boundary values via shuffle ---
            float xnr = __shfl_down_sync(0xFFFFFFFFu, X[0].x, 1);  // x_0 of lane+1
            float xni = __shfl_down_sync(0xFFFFFFFFu, X[0].y, 1);
            float ypr = __shfl_up_sync  (0xFFFFFFFFu, Y[3].x, 1);  // y_3 of lane-1
            float ypi = __shfl_up_sync  (0xFFFFFFFFu, Y[3].y, 1);

            float2 nx[4], ny[4];
            #pragma unroll
            for (int j = 0; j < 3; j++) {   // internal couplings (y_j, x_{j+1})
                ny[j].x   = CS * Y[j].x   - CN * X[j+1].y;
                ny[j].y   = CS * Y[j].y   + CN * X[j+1].x;
                nx[j+1].x = CS * X[j+1].x - CN * Y[j].y;
                nx[j+1].y = CS * X[j+1].y + CN * Y[j].x;
            }
            if (lane < 31) {                // (y_3, x_0 of lane+1)
                ny[3].x = CS * Y[3].x - CN * xni;
                ny[3].y = CS * Y[3].y + CN * xnr;
            } else {                        // global row N-1 pass-through
                ny[3].x = THRU * Y[3].x;
                ny[3].y = THRU * Y[3].y;
            }
            if (lane > 0) {                 // (y_3 of lane-1, x_0)
                nx[0].x = CS * X[0].x - CN * ypi;
                nx[0].y = CS * X[0].y + CN * ypr;
            } else {                        // global row 0 pass-through
                nx[0].x = THRU * X[0].x;
                nx[0].y = THRU * X[0].y;
            }
            #pragma unroll
            for (int j = 0; j < 4; j++) { X[j] = nx[j]; Y[j] = ny[j]; }
        }

        #pragma unroll
        for (int j = 0; j < 4; j++) ph[j] = phn[j];
    }

    // Final phase layer (129, already in ph); store REAL PART, row-major.
    #pragma unroll
    for (int j = 0; j < 4; j++) {
        float2 x = X[j], y = Y[j];
        float4 p = ph[j];
        float xr = p.x * x.x - p.y * x.y;   // Re(p0 * x)
        float yr = p.z * y.x - p.w * y.y;   // Re(p1 * y)
        int r0 = 8 * lane + 2 * j;
        out[r0 * N + col]       = xr;
        out[(r0 + 1) * N + col] = yr;
    }
}

extern "C" void kernel_launch(void* const* d_in, const int* in_sizes, int n_in,
                              void* d_out, int out_size) {
    const float* thetas = (const float*)d_in[0];
    int n = in_sizes[0];  // 130 * 256 = 33280

    phase_kernel<<<(n + 255) / 256, 256>>>(thetas, n);
    mesh_kernel<<<N, 32>>>((float*)d_out);
}